// round 16
// baseline (speedup 1.0000x reference)
#include <cuda_runtime.h>
#include <math_constants.h>

#define BB 2
#define NN 2048
#define MM 512
#define GG 27
#define CAGG 32
#define CPOST 128
#define GC (GG*CAGG)      // 864
#define BM (BB*MM)        // 1024
#define NCENT (BM*GG)     // 27648
#define NCELL 512         // 8^3 grid
#define HCELL 1.25f
#define INVH 0.8f
#define KSPLIT 27

// Scratch (device globals; allocation is forbidden)
__device__ __align__(16) float4 g_pts4[BB][NN];          // binned points
__device__ int   g_cstart[BB][NCELL+1];
__device__ int   g_perm[BB][NN];
__device__ __align__(16) float g_feats[BB*NN*32];        // binned reduced feats
__device__ __align__(16) float g_wT[GG*41*CAGG];         // weights [g][i][o]
__device__ __align__(16) float g_sc1[GC], g_sh1[GC];     // folded BN1
__device__ __align__(16) float g_x[BM*GC];               // grouped-conv out
__device__ __align__(16) float g_part[KSPLIT][BM*CPOST]; // split-K partials

// ---------------------------------------------------------------------------
// K_pre: blocks 0..BB-1: per-batch counting sort (1024 threads).
//        blocks BB.. : weight transpose [g][i][o] + BN1 fold.
// ---------------------------------------------------------------------------
__global__ __launch_bounds__(1024) void k_pre(
        const float* __restrict__ sxyz, const float* __restrict__ wg,
        const float* __restrict__ g1, const float* __restrict__ b1,
        const float* __restrict__ mu1, const float* __restrict__ v1) {
    const int tid = threadIdx.x;
    if (blockIdx.x >= BB) {
        int t = (blockIdx.x - BB) * 1024 + tid;
        if (t < GG*41*CAGG) {
            int g = t / (41*CAGG);
            int rm = t - g*(41*CAGG);
            int i = rm >> 5, o = rm & 31;
            g_wT[t] = wg[g*(CAGG*41) + o*41 + i];
        }
        if (t < GC) {
            float sc = g1[t] * rsqrtf(v1[t] + 1e-5f);
            g_sc1[t] = sc;
            g_sh1[t] = b1[t] - mu1[t]*sc;
        }
        return;
    }
    __shared__ int cnt[NCELL];
    __shared__ int start[NCELL+1];
    const int b = blockIdx.x;
    for (int c = tid; c < NCELL; c += 1024) cnt[c] = 0;
    __syncthreads();
    for (int p = tid; p < NN; p += 1024) {
        const float* s = sxyz + (b*NN + p)*3;
        int cx = min(max((int)floorf(s[0]*INVH), 0), 7);
        int cy = min(max((int)floorf(s[1]*INVH), 0), 7);
        int cz = min(max((int)floorf(s[2]*INVH), 0), 7);
        atomicAdd(&cnt[(cx*8+cy)*8+cz], 1);
    }
    __syncthreads();
    if (tid < 32) {                      // warp-serial prefix over 512 cells
        int base = tid*16, s = 0;
        #pragma unroll
        for (int i = 0; i < 16; ++i) s += cnt[base+i];
        int inc = s;
        #pragma unroll
        for (int o = 1; o < 32; o <<= 1) {
            int v = __shfl_up_sync(0xffffffffu, inc, o);
            if (tid >= o) inc += v;
        }
        int run = inc - s;
        #pragma unroll
        for (int i = 0; i < 16; ++i) { start[base+i] = run; run += cnt[base+i]; }
        if (tid == 31) start[NCELL] = run;
    }
    __syncthreads();
    for (int c = tid; c < NCELL; c += 1024) cnt[c] = start[c];
    __syncthreads();
    for (int p = tid; p < NN; p += 1024) {
        const float* s = sxyz + (b*NN + p)*3;
        float x = s[0], y = s[1], z = s[2];
        int cx = min(max((int)floorf(x*INVH), 0), 7);
        int cy = min(max((int)floorf(y*INVH), 0), 7);
        int cz = min(max((int)floorf(z*INVH), 0), 7);
        int pos = atomicAdd(&cnt[(cx*8+cy)*8+cz], 1);
        g_pts4[b][pos] = make_float4(x, y, z, 0.0f);
        g_perm[b][pos] = p;
    }
    for (int c = tid; c <= NCELL; c += 1024) g_cstart[b][c] = start[c];
}

// ---------------------------------------------------------------------------
// K_reduce: channel reduction 128->32 gathered into binned order (float4)
// ---------------------------------------------------------------------------
__global__ void k_reduce(const float* __restrict__ sf) {
    int t = blockIdx.x * 256 + threadIdx.x;
    if (t >= BB*NN*8) return;
    int row = t >> 3, c4 = t & 7;
    int b = row / NN, p = row - b*NN;
    int orig = g_perm[b][p];
    const float4* q = (const float4*)(sf + (b*NN + orig)*128) + c4;
    float4 v0 = __ldg(q);
    float4 v1 = __ldg(q + 8);
    float4 v2 = __ldg(q + 16);
    float4 v3 = __ldg(q + 24);
    float4 s;
    s.x = (v0.x + v1.x) + (v2.x + v3.x);
    s.y = (v0.y + v1.y) + (v2.y + v3.y);
    s.z = (v0.z + v1.z) + (v2.z + v3.z);
    s.w = (v0.w + v1.w) + (v2.w + v3.w);
    ((float4*)g_feats)[row*8 + c4] = s;
}

// Branchless insert of (d,i) into sorted triple d0<=d1<=d2
__device__ __forceinline__ void ins3(float d, int i,
        float& d0, int& i0, float& d1, int& i1, float& d2, int& i2) {
    bool c2 = d < d2, c1 = d < d1, c0 = d < d0;
    d2 = c1 ? d1 : (c2 ? d : d2);  i2 = c1 ? i1 : (c2 ? i : i2);
    d1 = c0 ? d0 : (c1 ? d : d1);  i1 = c0 ? i0 : (c1 ? i : i1);
    d0 = c0 ? d  : d0;             i0 = c0 ? i  : i0;
}

// ---------------------------------------------------------------------------
// K_nn: grid 3-NN per center (16-lane groups) + interp + FUSED grouped conv
// + BN1 + ReLU. RADIUS-driven tight cell box (start 0.9 + outside-dist,
// escalate x1.8, cap 4.8=QR); z-run scan with prev-box subtraction; exact
// count-based termination; top-3 via 3 group-min pops. Writes g_x.
// ---------------------------------------------------------------------------
__global__ __launch_bounds__(256) void k_nn(const float* __restrict__ nxyz) {
    __shared__ __align__(16) float sv[16][48];   // staged vec[41] per group
    __shared__ int cst[NCELL+1];
    const int tid = threadIdx.x;
    const int grp = tid >> 4;
    const int l   = tid & 15;
    const unsigned gmask = 0xffffu << (tid & 16);   // group-local mask
    const int cid = blockIdx.x*16 + grp;
    const int b   = (blockIdx.x*16) / (MM*GG);   // never straddles batches

    for (int i = tid; i < NCELL+1; i += 256) cst[i] = g_cstart[b][i];
    __syncthreads();

    const int m = cid / GG, g = cid - m*GG;
    const int ixg = g / 9;
    const int iyg = (g - ixg*9) / 3;
    const int izg = g - ixg*9 - iyg*3;
    const float cx = nxyz[m*3+0] + __fadd_rn(__fmul_rn((float)ixg + 0.5f, 1.6f), -2.4f);
    const float cy = nxyz[m*3+1] + __fadd_rn(__fmul_rn((float)iyg + 0.5f, 1.6f), -2.4f);
    const float cz = nxyz[m*3+2] + __fadd_rn(__fmul_rn((float)izg + 0.5f, 1.6f), -2.4f);

    const float INF = CUDART_INF_F;
    float d0 = INF, d1 = INF, d2v = INF;   // per-lane triple (disjoint sets)
    int   i0 = -1,  i1 = -1,  i2 = -1;

    const float4* __restrict__ pts = g_pts4[b];

    // initial radius: median-3NN pad + distance outside the [0,10] domain
    {
        float ox = fmaxf(fmaxf(-cx, cx - 10.0f), 0.0f);
        float oy = fmaxf(fmaxf(-cy, cy - 10.0f), 0.0f);
        float oz = fmaxf(fmaxf(-cz, cz - 10.0f), 0.0f);
        float rad = 0.9f + sqrtf(fmaf(ox, ox, fmaf(oy, oy, oz*oz)));
        rad = fminf(rad, 4.8f);

        int pxlo = 1, pxhi = 0, pylo = 1, pyhi = 0, pzlo = 1, pzhi = 0;
        bool havePrev = false;

        for (int it = 0; it < 8; ++it) {
            const int nxlo = max((int)floorf((cx - rad)*INVH), 0);
            const int nxhi = min((int)floorf((cx + rad)*INVH), 7);
            const int nylo = max((int)floorf((cy - rad)*INVH), 0);
            const int nyhi = min((int)floorf((cy + rad)*INVH), 7);
            const int nzlo = max((int)floorf((cz - rad)*INVH), 0);
            const int nzhi = min((int)floorf((cz + rad)*INVH), 7);
            const bool valid = (nxlo <= nxhi) && (nylo <= nyhi) && (nzlo <= nzhi);
            if (valid) {
                for (int x = nxlo; x <= nxhi; ++x)
                for (int y = nylo; y <= nyhi; ++y) {
                    const int base = (x*8 + y)*8;
                    const bool rowPrev = havePrev &&
                        x >= pxlo && x <= pxhi && y >= pylo && y <= pyhi;
                    int al, ah, bl, bh;
                    if (rowPrev) { al = nzlo; ah = pzlo-1; bl = pzhi+1; bh = nzhi; }
                    else         { al = nzlo; ah = nzhi;   bl = 1;      bh = 0;   }
                    if (ah >= al) {
                        const int s = cst[base+al], e = cst[base+ah+1];
                        for (int j = s + l; j < e; j += 16) {
                            float4 p = __ldg(&pts[j]);
                            float dx = cx - p.x, dy = cy - p.y, dz = cz - p.z;
                            float dsq = fmaf(dx, dx, fmaf(dy, dy, dz*dz));
                            float ch  = fmaxf(fabsf(dx), fmaxf(fabsf(dy), fabsf(dz)));
                            float dd  = (ch <= 4.8f) ? dsq : INF;
                            ins3(dd, j, d0, i0, d1, i1, d2v, i2);
                        }
                    }
                    if (bh >= bl) {
                        const int s = cst[base+bl], e = cst[base+bh+1];
                        for (int j = s + l; j < e; j += 16) {
                            float4 p = __ldg(&pts[j]);
                            float dx = cx - p.x, dy = cy - p.y, dz = cz - p.z;
                            float dsq = fmaf(dx, dx, fmaf(dy, dy, dz*dz));
                            float ch  = fmaxf(fabsf(dx), fmaxf(fabsf(dy), fabsf(dz)));
                            float dd  = (ch <= 4.8f) ? dsq : INF;
                            ins3(dd, j, d0, i0, d1, i1, d2v, i2);
                        }
                    }
                }
                pxlo = nxlo; pxhi = nxhi; pylo = nylo; pyhi = nyhi;
                pzlo = nzlo; pzhi = nzhi; havePrev = true;
            }
            if (rad >= 4.8f - 1e-6f) break;    // all cube-filter candidates seen
            float bound = rad - 1e-3f;         // fp cell-assignment margin
            float b2 = bound * bound;
            unsigned cnt = (unsigned)(d0 < b2) + (unsigned)(d1 < b2)
                         + (unsigned)(d2v < b2);
            if (__reduce_add_sync(gmask, cnt) >= 3) break;
            rad = fminf(rad * 1.8f, 4.8f);
        }
    }

    // top-3 via 3 successive group-min pops (positive floats order as u32)
    float td[3]; int ti[3];
    #pragma unroll
    for (int k = 0; k < 3; ++k) {
        unsigned kbits = __reduce_min_sync(gmask, __float_as_uint(d0));
        unsigned ball  = __ballot_sync(gmask, __float_as_uint(d0) == kbits);
        int src = __ffs(ball) - 1;                      // absolute lane id
        td[k] = __uint_as_float(kbits);
        ti[k] = __shfl_sync(gmask, i0, src);
        if ((tid & 31) == src) { d0 = d1; i0 = i1; d1 = d2v; i1 = i2; d2v = INF; i2 = -1; }
    }

    const bool empty = !(td[0] < INF);
    float r0 = (td[0] < INF) ? 1.0f/(td[0] + 1e-8f) : 0.0f;
    float r1 = (td[1] < INF) ? 1.0f/(td[1] + 1e-8f) : 0.0f;
    float r2 = (td[2] < INF) ? 1.0f/(td[2] + 1e-8f) : 0.0f;
    float ssum = fmaxf(r0 + r1 + r2, 1e-8f);
    float w0 = r0/ssum, w1 = r1/ssum, w2 = r2/ssum;
    int ti0 = ti[0] < 0 ? 0 : ti[0];
    int ti1 = ti[1] < 0 ? ti0 : ti[1];
    int ti2 = ti[2] < 0 ? ti0 : ti[2];

    // interp: lane handles 2 feature channels (float2) -> stage to smem
    {
        const float2* F0 = (const float2*)(g_feats + (b*NN + ti0)*32);
        const float2* F1 = (const float2*)(g_feats + (b*NN + ti1)*32);
        const float2* F2 = (const float2*)(g_feats + (b*NN + ti2)*32);
        float2 a = __ldg(&F0[l]), u = __ldg(&F1[l]), v = __ldg(&F2[l]);
        float2 f;
        f.x = empty ? 0.0f : (w0*a.x + w1*u.x + w2*v.x);
        f.y = empty ? 0.0f : (w0*a.y + w1*u.y + w2*v.y);
        ((float2*)sv[grp])[l] = f;
        if (l < 3) {
            int isel = (l == 0) ? ti0 : ((l == 1) ? ti1 : ti2);
            float4 p = __ldg(&pts[isel]);
            sv[grp][32 + l*3 + 0] = empty ? 0.0f : (cx - p.x);
            sv[grp][32 + l*3 + 1] = empty ? 0.0f : (cy - p.y);
            sv[grp][32 + l*3 + 2] = empty ? 0.0f : (cz - p.z);
        }
    }
    __syncwarp();

    // fused grouped conv: lane computes output channels 2l, 2l+1
    const float* wrow = g_wT + g*(41*CAGG) + 2*l;
    float a0 = 0.0f, a1 = 0.0f;
    #pragma unroll
    for (int i = 0; i < 41; ++i) {
        float vi = sv[grp][i];
        float2 w = *(const float2*)(wrow + i*CAGG);
        a0 = fmaf(vi, w.x, a0);
        a1 = fmaf(vi, w.y, a1);
    }
    const int gc = g*CAGG + 2*l;
    float2 r;
    r.x = fmaxf(fmaf(a0, __ldg(&g_sc1[gc]),   __ldg(&g_sh1[gc])),   0.0f);
    r.y = fmaxf(fmaf(a1, __ldg(&g_sc1[gc+1]), __ldg(&g_sh1[gc+1])), 0.0f);
    *(float2*)(g_x + m*GC + gc) = r;
}

// ---------------------------------------------------------------------------
// K_post: split-K GEMM partials. CTA tile 32m x 64n, ONE k-chunk of 32.
// block 128: nq = tid&15 (16 x 4n), mq = tid>>4 (8 x 4m). 4x4 regs.
// grid (32, 2, 27) = 1728 CTAs (~12 CTAs/SM).
// ---------------------------------------------------------------------------
__global__ __launch_bounds__(128) void k_post(const float* __restrict__ wp) {
    __shared__ float sA[32][36];    // [k][m] pitch 36 (16B-aligned rows)
    __shared__ float sB[32][68];    // [k][n] pitch 68
    const int tid = threadIdx.x;
    const int nq = tid & 15;
    const int mq = tid >> 4;
    const int m0 = blockIdx.x * 32;
    const int c0 = blockIdx.y * 64;
    const int kb = blockIdx.z * 32;

    // A: 32m x 32k = 256 float4; 128 threads x 2
    #pragma unroll
    for (int i = 0; i < 2; ++i) {
        int f = tid + i*128;
        int mm = f >> 3, kq = (f & 7) << 2;
        float4 vv = *(const float4*)(g_x + (m0+mm)*GC + kb + kq);
        sA[kq+0][mm] = vv.x; sA[kq+1][mm] = vv.y;
        sA[kq+2][mm] = vv.z; sA[kq+3][mm] = vv.w;
    }
    // B: 64n x 32k = 512 float4; 128 threads x 4
    #pragma unroll
    for (int i = 0; i < 4; ++i) {
        int f = tid + i*128;
        int nr = f >> 3, kq = (f & 7) << 2;
        float4 vv = *(const float4*)(wp + (c0+nr)*GC + kb + kq);
        sB[kq+0][nr] = vv.x; sB[kq+1][nr] = vv.y;
        sB[kq+2][nr] = vv.z; sB[kq+3][nr] = vv.w;
    }
    __syncthreads();

    float acc[4][4];
    #pragma unroll
    for (int i = 0; i < 4; ++i)
        #pragma unroll
        for (int j = 0; j < 4; ++j) acc[i][j] = 0.0f;

    #pragma unroll
    for (int k = 0; k < 32; ++k) {
        float av[4], bv[4];
        *(float4*)&av[0] = *(const float4*)&sA[k][mq*4];
        *(float4*)&bv[0] = *(const float4*)&sB[k][nq*4];
        #pragma unroll
        for (int i = 0; i < 4; ++i)
            #pragma unroll
            for (int j = 0; j < 4; ++j)
                acc[i][j] = fmaf(av[i], bv[j], acc[i][j]);
    }

    float* dst = g_part[blockIdx.z];
    #pragma unroll
    for (int i = 0; i < 4; ++i) {
        int mrow = m0 + mq*4 + i;
        *(float4*)(dst + mrow*CPOST + c0 + nq*4) = *(float4*)&acc[i][0];
    }
}

// ---------------------------------------------------------------------------
// K_fin: sum split-K partials + BN2 + ReLU
// ---------------------------------------------------------------------------
__global__ void k_fin(const float* __restrict__ g2, const float* __restrict__ b2,
                      const float* __restrict__ mu2, const float* __restrict__ v2,
                      float* __restrict__ out) {
    int t = blockIdx.x * 256 + threadIdx.x;
    if (t >= BM*CPOST) return;
    int c = t & 127;
    float s = 0.0f;
    #pragma unroll
    for (int k = 0; k < KSPLIT; ++k) s += g_part[k][t];
    float scale = g2[c] * rsqrtf(v2[c] + 1e-5f);
    float shift = b2[c] - mu2[c]*scale;
    out[t] = fmaxf(fmaf(s, scale, shift), 0.0f);
}

// ---------------------------------------------------------------------------
extern "C" void kernel_launch(void* const* d_in, const int* in_sizes, int n_in,
                              void* d_out, int out_size) {
    const float* sxyz  = (const float*)d_in[0];
    const float* sfeat = (const float*)d_in[1];
    const float* nxyz  = (const float*)d_in[2];
    const float* wg    = (const float*)d_in[3];
    const float* g1    = (const float*)d_in[4];
    const float* b1    = (const float*)d_in[5];
    const float* m1    = (const float*)d_in[6];
    const float* v1    = (const float*)d_in[7];
    const float* wp    = (const float*)d_in[8];
    const float* g2    = (const float*)d_in[9];
    const float* b2    = (const float*)d_in[10];
    const float* m2    = (const float*)d_in[11];
    const float* v2    = (const float*)d_in[12];
    float* out = (float*)d_out;

    const int wtBlocks = (GG*41*CAGG + 1023) / 1024;      // 35
    k_pre<<<BB + wtBlocks, 1024>>>(sxyz, wg, g1, b1, m1, v1);
    k_reduce<<<(BB*NN*8 + 255)/256, 256>>>(sfeat);
    k_nn<<<NCENT/16, 256>>>(nxyz);
    k_post<<<dim3(BM/32, CPOST/64, KSPLIT), 128>>>(wp);
    k_fin<<<(BM*CPOST + 255)/256, 256>>>(g2, b2, m2, v2, out);
}

// round 17
// speedup vs baseline: 1.0332x; 1.0332x over previous
#include <cuda_runtime.h>
#include <math_constants.h>

#define BB 2
#define NN 2048
#define MM 512
#define GG 27
#define CAGG 32
#define CPOST 128
#define GC (GG*CAGG)      // 864
#define BM (BB*MM)        // 1024
#define NCENT (BM*GG)     // 27648
#define NCELL 512         // 8^3 grid
#define HCELL 1.25f
#define INVH 0.8f
#define KSPLIT 27

// Scratch (device globals; allocation is forbidden)
__device__ __align__(16) float4 g_pts4[BB][NN];          // binned points
__device__ int   g_cstart[BB][NCELL+1];
__device__ int   g_perm[BB][NN];
__device__ __align__(16) float g_feats[BB*NN*32];        // binned reduced feats
__device__ __align__(16) float g_wT[GG*41*CAGG];         // weights [g][i][o]
__device__ __align__(16) float g_sc1[GC], g_sh1[GC];     // folded BN1
__device__ __align__(16) float g_x[BM*GC];               // grouped-conv out
__device__ __align__(16) float g_part[KSPLIT][BM*CPOST]; // split-K partials

// ---------------------------------------------------------------------------
// K_pre: blocks 0..BB-1: per-batch counting sort (1024 threads).
//        blocks BB.. : weight transpose [g][i][o] + BN1 fold.
// ---------------------------------------------------------------------------
__global__ __launch_bounds__(1024) void k_pre(
        const float* __restrict__ sxyz, const float* __restrict__ wg,
        const float* __restrict__ g1, const float* __restrict__ b1,
        const float* __restrict__ mu1, const float* __restrict__ v1) {
    const int tid = threadIdx.x;
    if (blockIdx.x >= BB) {
        int t = (blockIdx.x - BB) * 1024 + tid;
        if (t < GG*41*CAGG) {
            int g = t / (41*CAGG);
            int rm = t - g*(41*CAGG);
            int i = rm >> 5, o = rm & 31;
            g_wT[t] = wg[g*(CAGG*41) + o*41 + i];
        }
        if (t < GC) {
            float sc = g1[t] * rsqrtf(v1[t] + 1e-5f);
            g_sc1[t] = sc;
            g_sh1[t] = b1[t] - mu1[t]*sc;
        }
        return;
    }
    __shared__ int cnt[NCELL];
    __shared__ int start[NCELL+1];
    const int b = blockIdx.x;
    for (int c = tid; c < NCELL; c += 1024) cnt[c] = 0;
    __syncthreads();
    for (int p = tid; p < NN; p += 1024) {
        const float* s = sxyz + (b*NN + p)*3;
        int cx = min(max((int)floorf(s[0]*INVH), 0), 7);
        int cy = min(max((int)floorf(s[1]*INVH), 0), 7);
        int cz = min(max((int)floorf(s[2]*INVH), 0), 7);
        atomicAdd(&cnt[(cx*8+cy)*8+cz], 1);
    }
    __syncthreads();
    if (tid < 32) {                      // warp-serial prefix over 512 cells
        int base = tid*16, s = 0;
        #pragma unroll
        for (int i = 0; i < 16; ++i) s += cnt[base+i];
        int inc = s;
        #pragma unroll
        for (int o = 1; o < 32; o <<= 1) {
            int v = __shfl_up_sync(0xffffffffu, inc, o);
            if (tid >= o) inc += v;
        }
        int run = inc - s;
        #pragma unroll
        for (int i = 0; i < 16; ++i) { start[base+i] = run; run += cnt[base+i]; }
        if (tid == 31) start[NCELL] = run;
    }
    __syncthreads();
    for (int c = tid; c < NCELL; c += 1024) cnt[c] = start[c];
    __syncthreads();
    for (int p = tid; p < NN; p += 1024) {
        const float* s = sxyz + (b*NN + p)*3;
        float x = s[0], y = s[1], z = s[2];
        int cx = min(max((int)floorf(x*INVH), 0), 7);
        int cy = min(max((int)floorf(y*INVH), 0), 7);
        int cz = min(max((int)floorf(z*INVH), 0), 7);
        int pos = atomicAdd(&cnt[(cx*8+cy)*8+cz], 1);
        g_pts4[b][pos] = make_float4(x, y, z, 0.0f);
        g_perm[b][pos] = p;
    }
    for (int c = tid; c <= NCELL; c += 1024) g_cstart[b][c] = start[c];
}

// ---------------------------------------------------------------------------
// K_reduce: channel reduction 128->32 gathered into binned order (float4)
// ---------------------------------------------------------------------------
__global__ void k_reduce(const float* __restrict__ sf) {
    int t = blockIdx.x * 256 + threadIdx.x;
    if (t >= BB*NN*8) return;
    int row = t >> 3, c4 = t & 7;
    int b = row / NN, p = row - b*NN;
    int orig = g_perm[b][p];
    const float4* q = (const float4*)(sf + (b*NN + orig)*128) + c4;
    float4 v0 = __ldg(q);
    float4 v1 = __ldg(q + 8);
    float4 v2 = __ldg(q + 16);
    float4 v3 = __ldg(q + 24);
    float4 s;
    s.x = (v0.x + v1.x) + (v2.x + v3.x);
    s.y = (v0.y + v1.y) + (v2.y + v3.y);
    s.z = (v0.z + v1.z) + (v2.z + v3.z);
    s.w = (v0.w + v1.w) + (v2.w + v3.w);
    ((float4*)g_feats)[row*8 + c4] = s;
}

// Branchless insert of (d,i) into sorted triple d0<=d1<=d2
__device__ __forceinline__ void ins3(float d, int i,
        float& d0, int& i0, float& d1, int& i1, float& d2, int& i2) {
    bool c2 = d < d2, c1 = d < d1, c0 = d < d0;
    d2 = c1 ? d1 : (c2 ? d : d2);  i2 = c1 ? i1 : (c2 ? i : i2);
    d1 = c0 ? d0 : (c1 ? d : d1);  i1 = c0 ? i0 : (c1 ? i : i1);
    d0 = c0 ? d  : d0;             i0 = c0 ? i  : i0;
}

// ---------------------------------------------------------------------------
// K_nn: grid 3-NN per center (16-lane groups) + interp + FUSED grouped conv
// + BN1 + ReLU. RADIUS-driven tight cell box (start 0.9 + outside-dist,
// escalate x1.8, cap 4.8=QR); z-run scan with prev-box subtraction; exact
// count-based termination; top-3 via 3 group-min pops. Writes g_x.
// (R16 configuration — measured ~34.5us)
// ---------------------------------------------------------------------------
__global__ __launch_bounds__(256) void k_nn(const float* __restrict__ nxyz) {
    __shared__ __align__(16) float sv[16][48];   // staged vec[41] per group
    __shared__ int cst[NCELL+1];
    const int tid = threadIdx.x;
    const int grp = tid >> 4;
    const int l   = tid & 15;
    const unsigned gmask = 0xffffu << (tid & 16);   // group-local mask
    const int cid = blockIdx.x*16 + grp;
    const int b   = (blockIdx.x*16) / (MM*GG);   // never straddles batches

    for (int i = tid; i < NCELL+1; i += 256) cst[i] = g_cstart[b][i];
    __syncthreads();

    const int m = cid / GG, g = cid - m*GG;
    const int ixg = g / 9;
    const int iyg = (g - ixg*9) / 3;
    const int izg = g - ixg*9 - iyg*3;
    const float cx = nxyz[m*3+0] + __fadd_rn(__fmul_rn((float)ixg + 0.5f, 1.6f), -2.4f);
    const float cy = nxyz[m*3+1] + __fadd_rn(__fmul_rn((float)iyg + 0.5f, 1.6f), -2.4f);
    const float cz = nxyz[m*3+2] + __fadd_rn(__fmul_rn((float)izg + 0.5f, 1.6f), -2.4f);

    const float INF = CUDART_INF_F;
    float d0 = INF, d1 = INF, d2v = INF;   // per-lane triple (disjoint sets)
    int   i0 = -1,  i1 = -1,  i2 = -1;

    const float4* __restrict__ pts = g_pts4[b];

    // initial radius: median-3NN pad + distance outside the [0,10] domain
    {
        float ox = fmaxf(fmaxf(-cx, cx - 10.0f), 0.0f);
        float oy = fmaxf(fmaxf(-cy, cy - 10.0f), 0.0f);
        float oz = fmaxf(fmaxf(-cz, cz - 10.0f), 0.0f);
        float rad = 0.9f + sqrtf(fmaf(ox, ox, fmaf(oy, oy, oz*oz)));
        rad = fminf(rad, 4.8f);

        int pxlo = 1, pxhi = 0, pylo = 1, pyhi = 0, pzlo = 1, pzhi = 0;
        bool havePrev = false;

        for (int it = 0; it < 8; ++it) {
            const int nxlo = max((int)floorf((cx - rad)*INVH), 0);
            const int nxhi = min((int)floorf((cx + rad)*INVH), 7);
            const int nylo = max((int)floorf((cy - rad)*INVH), 0);
            const int nyhi = min((int)floorf((cy + rad)*INVH), 7);
            const int nzlo = max((int)floorf((cz - rad)*INVH), 0);
            const int nzhi = min((int)floorf((cz + rad)*INVH), 7);
            const bool valid = (nxlo <= nxhi) && (nylo <= nyhi) && (nzlo <= nzhi);
            if (valid) {
                for (int x = nxlo; x <= nxhi; ++x)
                for (int y = nylo; y <= nyhi; ++y) {
                    const int base = (x*8 + y)*8;
                    const bool rowPrev = havePrev &&
                        x >= pxlo && x <= pxhi && y >= pylo && y <= pyhi;
                    int al, ah, bl, bh;
                    if (rowPrev) { al = nzlo; ah = pzlo-1; bl = pzhi+1; bh = nzhi; }
                    else         { al = nzlo; ah = nzhi;   bl = 1;      bh = 0;   }
                    if (ah >= al) {
                        const int s = cst[base+al], e = cst[base+ah+1];
                        for (int j = s + l; j < e; j += 16) {
                            float4 p = __ldg(&pts[j]);
                            float dx = cx - p.x, dy = cy - p.y, dz = cz - p.z;
                            float dsq = fmaf(dx, dx, fmaf(dy, dy, dz*dz));
                            float ch  = fmaxf(fabsf(dx), fmaxf(fabsf(dy), fabsf(dz)));
                            float dd  = (ch <= 4.8f) ? dsq : INF;
                            ins3(dd, j, d0, i0, d1, i1, d2v, i2);
                        }
                    }
                    if (bh >= bl) {
                        const int s = cst[base+bl], e = cst[base+bh+1];
                        for (int j = s + l; j < e; j += 16) {
                            float4 p = __ldg(&pts[j]);
                            float dx = cx - p.x, dy = cy - p.y, dz = cz - p.z;
                            float dsq = fmaf(dx, dx, fmaf(dy, dy, dz*dz));
                            float ch  = fmaxf(fabsf(dx), fmaxf(fabsf(dy), fabsf(dz)));
                            float dd  = (ch <= 4.8f) ? dsq : INF;
                            ins3(dd, j, d0, i0, d1, i1, d2v, i2);
                        }
                    }
                }
                pxlo = nxlo; pxhi = nxhi; pylo = nylo; pyhi = nyhi;
                pzlo = nzlo; pzhi = nzhi; havePrev = true;
            }
            if (rad >= 4.8f - 1e-6f) break;    // all cube-filter candidates seen
            float bound = rad - 1e-3f;         // fp cell-assignment margin
            float b2 = bound * bound;
            unsigned cnt = (unsigned)(d0 < b2) + (unsigned)(d1 < b2)
                         + (unsigned)(d2v < b2);
            if (__reduce_add_sync(gmask, cnt) >= 3) break;
            rad = fminf(rad * 1.8f, 4.8f);
        }
    }

    // top-3 via 3 successive group-min pops (positive floats order as u32)
    float td[3]; int ti[3];
    #pragma unroll
    for (int k = 0; k < 3; ++k) {
        unsigned kbits = __reduce_min_sync(gmask, __float_as_uint(d0));
        unsigned ball  = __ballot_sync(gmask, __float_as_uint(d0) == kbits);
        int src = __ffs(ball) - 1;                      // absolute lane id
        td[k] = __uint_as_float(kbits);
        ti[k] = __shfl_sync(gmask, i0, src);
        if ((tid & 31) == src) { d0 = d1; i0 = i1; d1 = d2v; i1 = i2; d2v = INF; i2 = -1; }
    }

    const bool empty = !(td[0] < INF);
    float r0 = (td[0] < INF) ? 1.0f/(td[0] + 1e-8f) : 0.0f;
    float r1 = (td[1] < INF) ? 1.0f/(td[1] + 1e-8f) : 0.0f;
    float r2 = (td[2] < INF) ? 1.0f/(td[2] + 1e-8f) : 0.0f;
    float ssum = fmaxf(r0 + r1 + r2, 1e-8f);
    float w0 = r0/ssum, w1 = r1/ssum, w2 = r2/ssum;
    int ti0 = ti[0] < 0 ? 0 : ti[0];
    int ti1 = ti[1] < 0 ? ti0 : ti[1];
    int ti2 = ti[2] < 0 ? ti0 : ti[2];

    // interp: lane handles 2 feature channels (float2) -> stage to smem
    {
        const float2* F0 = (const float2*)(g_feats + (b*NN + ti0)*32);
        const float2* F1 = (const float2*)(g_feats + (b*NN + ti1)*32);
        const float2* F2 = (const float2*)(g_feats + (b*NN + ti2)*32);
        float2 a = __ldg(&F0[l]), u = __ldg(&F1[l]), v = __ldg(&F2[l]);
        float2 f;
        f.x = empty ? 0.0f : (w0*a.x + w1*u.x + w2*v.x);
        f.y = empty ? 0.0f : (w0*a.y + w1*u.y + w2*v.y);
        ((float2*)sv[grp])[l] = f;
        if (l < 3) {
            int isel = (l == 0) ? ti0 : ((l == 1) ? ti1 : ti2);
            float4 p = __ldg(&pts[isel]);
            sv[grp][32 + l*3 + 0] = empty ? 0.0f : (cx - p.x);
            sv[grp][32 + l*3 + 1] = empty ? 0.0f : (cy - p.y);
            sv[grp][32 + l*3 + 2] = empty ? 0.0f : (cz - p.z);
        }
    }
    __syncwarp();

    // fused grouped conv: lane computes output channels 2l, 2l+1
    const float* wrow = g_wT + g*(41*CAGG) + 2*l;
    float a0 = 0.0f, a1 = 0.0f;
    #pragma unroll
    for (int i = 0; i < 41; ++i) {
        float vi = sv[grp][i];
        float2 w = *(const float2*)(wrow + i*CAGG);
        a0 = fmaf(vi, w.x, a0);
        a1 = fmaf(vi, w.y, a1);
    }
    const int gc = g*CAGG + 2*l;
    float2 r;
    r.x = fmaxf(fmaf(a0, __ldg(&g_sc1[gc]),   __ldg(&g_sh1[gc])),   0.0f);
    r.y = fmaxf(fmaf(a1, __ldg(&g_sc1[gc+1]), __ldg(&g_sh1[gc+1])), 0.0f);
    *(float2*)(g_x + m*GC + gc) = r;
}

// ---------------------------------------------------------------------------
// K_post: split-K GEMM partials. CTA tile 64m x 64n, ONE k-chunk of 32.
// block 128: nq = tid&15 (16 x 4n), mq = tid>>4 (8 x 8m). 8x4 regs.
// grid (16, 2, 27) = 864 CTAs. (R15 configuration — measured 10.7us)
// ---------------------------------------------------------------------------
__global__ __launch_bounds__(128) void k_post(const float* __restrict__ wp) {
    __shared__ float sA[32][68];    // [k][m] pitch 68 (16B-aligned rows)
    __shared__ float sB[32][68];    // [k][n]
    const int tid = threadIdx.x;
    const int nq = tid & 15;
    const int mq = tid >> 4;
    const int m0 = blockIdx.x * 64;
    const int c0 = blockIdx.y * 64;
    const int kb = blockIdx.z * 32;

    // A: 64m x 32k = 512 float4; 128 threads x 4
    #pragma unroll
    for (int i = 0; i < 4; ++i) {
        int f = tid + i*128;
        int mm = f >> 3, kq = (f & 7) << 2;
        float4 vv = *(const float4*)(g_x + (m0+mm)*GC + kb + kq);
        sA[kq+0][mm] = vv.x; sA[kq+1][mm] = vv.y;
        sA[kq+2][mm] = vv.z; sA[kq+3][mm] = vv.w;
    }
    // B: 64n x 32k = 512 float4; 128 threads x 4
    #pragma unroll
    for (int i = 0; i < 4; ++i) {
        int f = tid + i*128;
        int nr = f >> 3, kq = (f & 7) << 2;
        float4 vv = *(const float4*)(wp + (c0+nr)*GC + kb + kq);
        sB[kq+0][nr] = vv.x; sB[kq+1][nr] = vv.y;
        sB[kq+2][nr] = vv.z; sB[kq+3][nr] = vv.w;
    }
    __syncthreads();

    float acc[8][4];
    #pragma unroll
    for (int i = 0; i < 8; ++i)
        #pragma unroll
        for (int j = 0; j < 4; ++j) acc[i][j] = 0.0f;

    #pragma unroll
    for (int k = 0; k < 32; ++k) {
        float av[8], bv[4];
        *(float4*)&av[0] = *(const float4*)&sA[k][mq*8];
        *(float4*)&av[4] = *(const float4*)&sA[k][mq*8 + 4];
        *(float4*)&bv[0] = *(const float4*)&sB[k][nq*4];
        #pragma unroll
        for (int i = 0; i < 8; ++i)
            #pragma unroll
            for (int j = 0; j < 4; ++j)
                acc[i][j] = fmaf(av[i], bv[j], acc[i][j]);
    }

    float* dst = g_part[blockIdx.z];
    #pragma unroll
    for (int i = 0; i < 8; ++i) {
        int mrow = m0 + mq*8 + i;
        *(float4*)(dst + mrow*CPOST + c0 + nq*4) = *(float4*)&acc[i][0];
    }
}

// ---------------------------------------------------------------------------
// K_fin: sum split-K partials + BN2 + ReLU
// ---------------------------------------------------------------------------
__global__ void k_fin(const float* __restrict__ g2, const float* __restrict__ b2,
                      const float* __restrict__ mu2, const float* __restrict__ v2,
                      float* __restrict__ out) {
    int t = blockIdx.x * 256 + threadIdx.x;
    if (t >= BM*CPOST) return;
    int c = t & 127;
    float s = 0.0f;
    #pragma unroll
    for (int k = 0; k < KSPLIT; ++k) s += g_part[k][t];
    float scale = g2[c] * rsqrtf(v2[c] + 1e-5f);
    float shift = b2[c] - mu2[c]*scale;
    out[t] = fmaxf(fmaf(s, scale, shift), 0.0f);
}

// ---------------------------------------------------------------------------
extern "C" void kernel_launch(void* const* d_in, const int* in_sizes, int n_in,
                              void* d_out, int out_size) {
    const float* sxyz  = (const float*)d_in[0];
    const float* sfeat = (const float*)d_in[1];
    const float* nxyz  = (const float*)d_in[2];
    const float* wg    = (const float*)d_in[3];
    const float* g1    = (const float*)d_in[4];
    const float* b1    = (const float*)d_in[5];
    const float* m1    = (const float*)d_in[6];
    const float* v1    = (const float*)d_in[7];
    const float* wp    = (const float*)d_in[8];
    const float* g2    = (const float*)d_in[9];
    const float* b2    = (const float*)d_in[10];
    const float* m2    = (const float*)d_in[11];
    const float* v2    = (const float*)d_in[12];
    float* out = (float*)d_out;

    const int wtBlocks = (GG*41*CAGG + 1023) / 1024;      // 35
    k_pre<<<BB + wtBlocks, 1024>>>(sxyz, wg, g1, b1, m1, v1);
    k_reduce<<<(BB*NN*8 + 255)/256, 256>>>(sfeat);
    k_nn<<<NCENT/16, 256>>>(nxyz);
    k_post<<<dim3(BM/64, CPOST/64, KSPLIT), 128>>>(wp);
    k_fin<<<(BM*CPOST + 255)/256, 256>>>(g2, b2, m2, v2, out);
}